// round 1
// baseline (speedup 1.0000x reference)
#include <cuda_runtime.h>
#include <cstdint>

#define Nn 8192
#define KIN 512
#define Ff 256
#define ALPHA 0.2f

// ---------------- scratch (no allocations allowed) ----------------
__device__ float g_h[Nn * Ff];       // h = X @ W            (8 MB)
__device__ float g_sself[Nn];        // h @ a[:256]
__device__ float g_sneigh[Nn];       // h @ a[256:]
__device__ float g_smax;             // max_j s_neigh[j]

// ================= kernel 1: h = X @ W  =================
// M=8192, N=256, K=512. BM=BN=64, BK=32, 256 threads, 4x4 micro.
__global__ __launch_bounds__(256, 1) void gemm_h_kernel(
    const float* __restrict__ A, const float* __restrict__ B) {
    __shared__ float As[32][65];   // [k][m], padded vs 32-way STS conflicts
    __shared__ float Bs[32][64];   // [k][n]

    int tid = threadIdx.x;
    int tx = tid & 15, ty = tid >> 4;
    int m0 = blockIdx.y * 64, n0 = blockIdx.x * 64;

    float acc[4][4];
#pragma unroll
    for (int i = 0; i < 4; i++)
#pragma unroll
        for (int j = 0; j < 4; j++) acc[i][j] = 0.f;

    for (int k0 = 0; k0 < KIN; k0 += 32) {
#pragma unroll
        for (int v = 0; v < 8; v++) {
            int idx = v * 256 + tid;
            int m = idx >> 5, k = idx & 31;
            As[k][m] = A[(size_t)(m0 + m) * KIN + k0 + k];
        }
#pragma unroll
        for (int v = 0; v < 8; v++) {
            int idx = v * 256 + tid;
            int k = idx >> 6, n = idx & 63;
            Bs[k][n] = B[(size_t)(k0 + k) * Ff + n0 + n];
        }
        __syncthreads();
#pragma unroll
        for (int k = 0; k < 32; k++) {
            float a0[4], b0[4];
#pragma unroll
            for (int i = 0; i < 4; i++) a0[i] = As[k][ty * 4 + i];
            float4 bv = *(const float4*)&Bs[k][tx * 4];
            b0[0] = bv.x; b0[1] = bv.y; b0[2] = bv.z; b0[3] = bv.w;
#pragma unroll
            for (int i = 0; i < 4; i++)
#pragma unroll
                for (int j = 0; j < 4; j++) acc[i][j] += a0[i] * b0[j];
        }
        __syncthreads();
    }
#pragma unroll
    for (int i = 0; i < 4; i++) {
        float4 o = make_float4(acc[i][0], acc[i][1], acc[i][2], acc[i][3]);
        *(float4*)&g_h[(size_t)(m0 + ty * 4 + i) * Ff + n0 + tx * 4] = o;
    }
}

// ================= kernel 2: s_self / s_neigh =================
// one CTA (256 threads) per row
__global__ __launch_bounds__(256) void attn_vec_kernel(const float* __restrict__ a) {
    int i = blockIdx.x;
    int t = threadIdx.x;
    float v = g_h[(size_t)i * Ff + t];
    float p1 = v * a[t];
    float p2 = v * a[Ff + t];
#pragma unroll
    for (int o = 16; o; o >>= 1) {
        p1 += __shfl_down_sync(0xffffffffu, p1, o);
        p2 += __shfl_down_sync(0xffffffffu, p2, o);
    }
    __shared__ float s1[8], s2[8];
    if ((t & 31) == 0) { s1[t >> 5] = p1; s2[t >> 5] = p2; }
    __syncthreads();
    if (t == 0) {
        float a1 = 0.f, a2 = 0.f;
#pragma unroll
        for (int w = 0; w < 8; w++) { a1 += s1[w]; a2 += s2[w]; }
        g_sself[i] = a1;
        g_sneigh[i] = a2;
    }
}

// ================= kernel 3: global max of s_neigh =================
__global__ void smax_kernel() {
    int t = threadIdx.x;  // 1024
    float m = -1e30f;
    for (int j = t; j < Nn; j += 1024) m = fmaxf(m, g_sneigh[j]);
#pragma unroll
    for (int o = 16; o; o >>= 1) m = fmaxf(m, __shfl_down_sync(0xffffffffu, m, o));
    __shared__ float sm[32];
    if ((t & 31) == 0) sm[t >> 5] = m;
    __syncthreads();
    if (t == 0) {
        float mm = sm[0];
#pragma unroll
        for (int w = 1; w < 32; w++) mm = fmaxf(mm, sm[w]);
        g_smax = mm;
    }
}

// ================= kernel 4: fused masked softmax-GEMM =================
// out[i] = elu( (sum_j p_ij * h[j]) / sum_j p_ij )
// p_ij = adj[i][j]>0 ? exp( leaky(s_self[i]+s_neigh[j]) - m_i ) : 0
// m_i  = leaky(s_self[i] + max_j s_neigh[j])   (valid upper bound; softmax shift-invariant)
#define BM 64
#define KT 32
__global__ __launch_bounds__(256, 1) void attn_main_kernel(
    const int* __restrict__ adj, float* __restrict__ out) {
    __shared__ float h_s[KT][Ff];     // 32 KB
    __shared__ float p_s[BM][KT];     // 8 KB  [row][j] : writes conflict-free, reads broadcast
    __shared__ float z_s[BM];
    __shared__ float m_s[BM];
    __shared__ float ss_s[BM];

    int tid = threadIdx.x;
    int w = tid >> 5, lane = tid & 31;
    int r0 = blockIdx.x * BM;

    if (tid < BM) {
        float s = g_sself[r0 + tid];
        ss_s[tid] = s;
        float x = s + g_smax;
        m_s[tid] = (x >= 0.f) ? x : ALPHA * x;
        z_s[tid] = 0.f;
    }

    float acc[8][8];
#pragma unroll
    for (int i = 0; i < 8; i++)
#pragma unroll
        for (int j = 0; j < 8; j++) acc[i][j] = 0.f;

    __syncthreads();

    for (int j0 = 0; j0 < Nn; j0 += KT) {
        // ---- fill h tile (rows j0..j0+31 are contiguous in g_h) ----
        const float4* hsrc = (const float4*)g_h;
#pragma unroll
        for (int v = 0; v < 8; v++) {
            int e = v * 256 + tid;                       // float4 index in tile
            ((float4*)h_s)[e] = hsrc[(size_t)j0 * (Ff / 4) + e];
        }
        // ---- fill p tile: warp w owns rows w*8 .. w*8+7 ----
        float sn = g_sneigh[j0 + lane];
#pragma unroll
        for (int ri = 0; ri < 8; ri++) {
            int r = w * 8 + ri;
            int av = adj[(size_t)(r0 + r) * Nn + j0 + lane];
            float x = ss_s[r] + sn;
            float l = (x >= 0.f) ? x : ALPHA * x;
            float p = (av > 0) ? __expf(l - m_s[r]) : 0.f;
            p_s[r][lane] = p;
            float s = p;
#pragma unroll
            for (int o = 16; o; o >>= 1) s += __shfl_down_sync(0xffffffffu, s, o);
            if (lane == 0) z_s[r] += s;   // same warp owns row across all tiles: no race
        }
        __syncthreads();
        // ---- 64x256x32 fp32 MMA: thread = rows w*8+[0..7] x cols lane*8+[0..7] ----
#pragma unroll
        for (int k = 0; k < KT; k++) {
            float pf[8];
#pragma unroll
            for (int ri = 0; ri < 8; ri++) pf[ri] = p_s[w * 8 + ri][k];
            float4 h0 = *(const float4*)&h_s[k][lane * 8];
            float4 h1 = *(const float4*)&h_s[k][lane * 8 + 4];
            float hf[8] = {h0.x, h0.y, h0.z, h0.w, h1.x, h1.y, h1.z, h1.w};
#pragma unroll
            for (int ri = 0; ri < 8; ri++)
#pragma unroll
                for (int ci = 0; ci < 8; ci++) acc[ri][ci] += pf[ri] * hf[ci];
        }
        __syncthreads();
    }

    // ---- epilogue: divide by Z, ELU, store ----
#pragma unroll
    for (int ri = 0; ri < 8; ri++) {
        int r = w * 8 + ri;
        float invz = 1.0f / z_s[r];
        float o[8];
#pragma unroll
        for (int ci = 0; ci < 8; ci++) {
            float v = acc[ri][ci] * invz;
            o[ci] = (v > 0.f) ? v : expm1f(v);
        }
        float* dst = out + (size_t)(r0 + r) * Ff + lane * 8;
        *(float4*)dst = make_float4(o[0], o[1], o[2], o[3]);
        *(float4*)(dst + 4) = make_float4(o[4], o[5], o[6], o[7]);
    }
}

// ================= launcher =================
extern "C" void kernel_launch(void* const* d_in, const int* in_sizes, int n_in,
                              void* d_out, int out_size) {
    const float* input = (const float*)d_in[0];   // [8192, 512]
    const int*   adj   = (const int*)d_in[1];     // [8192, 8192]
    const float* W     = (const float*)d_in[2];   // [512, 256]
    const float* a     = (const float*)d_in[3];   // [512, 1]
    float* out = (float*)d_out;                   // [8192, 256]

    dim3 g1(Ff / 64, Nn / 64);
    gemm_h_kernel<<<g1, 256>>>(input, W);
    attn_vec_kernel<<<Nn, 256>>>(a);
    smax_kernel<<<1, 1024>>>();
    attn_main_kernel<<<Nn / BM, 256>>>(adj, out);
}

// round 2
// speedup vs baseline: 1.1258x; 1.1258x over previous
#include <cuda_runtime.h>
#include <cstdint>

#define Nn 8192
#define KIN 512
#define Ff 256
#define ALPHA 0.2f
#define BM 64
#define KT 32
#define NT (Nn / KT)
#define PSTR (BM + 4)   // p_s row stride in u64 (68*8=544 bytes, 16B aligned)

// ---------------- scratch ----------------
__device__ float g_h[Nn * Ff];
__device__ float g_sself[Nn];
__device__ float g_sneigh[Nn];
__device__ float g_e1[Nn];     // exp(s_neigh)
__device__ float g_e2[Nn];     // exp(0.2*s_neigh)
__device__ float g_smax;

// ---------------- packed f32x2 helpers ----------------
__device__ __forceinline__ unsigned long long ffma2(unsigned long long a,
                                                    unsigned long long b,
                                                    unsigned long long c) {
    unsigned long long d;
    asm("fma.rn.f32x2 %0, %1, %2, %3;" : "=l"(d) : "l"(a), "l"(b), "l"(c));
    return d;
}
__device__ __forceinline__ unsigned long long packdup(float p) {
    unsigned long long v;
    asm("mov.b64 %0, {%1, %1};" : "=l"(v) : "f"(p));
    return v;
}
__device__ __forceinline__ float2 unpack2(unsigned long long v) {
    float2 f;
    asm("mov.b64 {%0, %1}, %2;" : "=f"(f.x), "=f"(f.y) : "l"(v));
    return f;
}

// ================= kernel 1: h = X @ W =================
__global__ __launch_bounds__(256, 1) void gemm_h_kernel(
    const float* __restrict__ A, const float* __restrict__ B) {
    __shared__ float As[32][65];
    __shared__ float Bs[32][64];
    int tid = threadIdx.x;
    int tx = tid & 15, ty = tid >> 4;
    int m0 = blockIdx.y * 64, n0 = blockIdx.x * 64;
    float acc[4][4];
#pragma unroll
    for (int i = 0; i < 4; i++)
#pragma unroll
        for (int j = 0; j < 4; j++) acc[i][j] = 0.f;
    for (int k0 = 0; k0 < KIN; k0 += 32) {
#pragma unroll
        for (int v = 0; v < 8; v++) {
            int idx = v * 256 + tid;
            int m = idx >> 5, k = idx & 31;
            As[k][m] = A[(size_t)(m0 + m) * KIN + k0 + k];
        }
#pragma unroll
        for (int v = 0; v < 8; v++) {
            int idx = v * 256 + tid;
            int k = idx >> 6, n = idx & 63;
            Bs[k][n] = B[(size_t)(k0 + k) * Ff + n0 + n];
        }
        __syncthreads();
#pragma unroll
        for (int k = 0; k < 32; k++) {
            float a0[4], b0[4];
#pragma unroll
            for (int i = 0; i < 4; i++) a0[i] = As[k][ty * 4 + i];
            float4 bv = *(const float4*)&Bs[k][tx * 4];
            b0[0] = bv.x; b0[1] = bv.y; b0[2] = bv.z; b0[3] = bv.w;
#pragma unroll
            for (int i = 0; i < 4; i++)
#pragma unroll
                for (int j = 0; j < 4; j++) acc[i][j] += a0[i] * b0[j];
        }
        __syncthreads();
    }
#pragma unroll
    for (int i = 0; i < 4; i++) {
        float4 o = make_float4(acc[i][0], acc[i][1], acc[i][2], acc[i][3]);
        *(float4*)&g_h[(size_t)(m0 + ty * 4 + i) * Ff + n0 + tx * 4] = o;
    }
}

// ================= kernel 2: s_self / s_neigh (+ e1,e2) =================
__global__ __launch_bounds__(256) void attn_vec_kernel(const float* __restrict__ a) {
    int i = blockIdx.x;
    int t = threadIdx.x;
    float v = g_h[(size_t)i * Ff + t];
    float p1 = v * a[t];
    float p2 = v * a[Ff + t];
#pragma unroll
    for (int o = 16; o; o >>= 1) {
        p1 += __shfl_down_sync(0xffffffffu, p1, o);
        p2 += __shfl_down_sync(0xffffffffu, p2, o);
    }
    __shared__ float s1[8], s2[8];
    if ((t & 31) == 0) { s1[t >> 5] = p1; s2[t >> 5] = p2; }
    __syncthreads();
    if (t == 0) {
        float a1 = 0.f, a2 = 0.f;
#pragma unroll
        for (int w = 0; w < 8; w++) { a1 += s1[w]; a2 += s2[w]; }
        g_sself[i] = a1;
        g_sneigh[i] = a2;
        g_e1[i] = __expf(a2);
        g_e2[i] = __expf(ALPHA * a2);
    }
}

// ================= kernel 3: global max of s_neigh =================
__global__ void smax_kernel() {
    int t = threadIdx.x;
    float m = -1e30f;
    for (int j = t; j < Nn; j += 1024) m = fmaxf(m, g_sneigh[j]);
#pragma unroll
    for (int o = 16; o; o >>= 1) m = fmaxf(m, __shfl_down_sync(0xffffffffu, m, o));
    __shared__ float sm[32];
    if ((t & 31) == 0) sm[t >> 5] = m;
    __syncthreads();
    if (t == 0) {
        float mm = sm[0];
#pragma unroll
        for (int w = 1; w < 32; w++) mm = fmaxf(mm, sm[w]);
        g_smax = mm;
    }
}

// ================= kernel 4: fused masked softmax-GEMM =================
// p_ij = adj ? (x>=0 ? c1[i]*e1[j] : c2[i]*e2[j]) : 0,  x = ss[i]+sn[j]
// c1[i]=exp(ss[i]-m_i), c2[i]=exp(ALPHA*ss[i]-m_i), m_i=leaky(ss[i]+smax)
__global__ __launch_bounds__(256, 1) void attn_main_kernel(
    const int* __restrict__ adj, float* __restrict__ out) {
    extern __shared__ char smem_raw[];
    // [2][KT][Ff] floats = 64 KB, then p_s [KT][PSTR] u64 = 17 KB
    float (*h_s)[KT][Ff] = (float (*)[KT][Ff])smem_raw;
    unsigned long long (*p_s)[PSTR] =
        (unsigned long long (*)[PSTR])(smem_raw + 2 * KT * Ff * sizeof(float));

    __shared__ float c1_s[BM], c2_s[BM], thr_s[BM];

    int tid = threadIdx.x;
    int w = tid >> 5, lane = tid & 31;
    int r0 = blockIdx.x * BM;

    if (tid < BM) {
        float ss = g_sself[r0 + tid];
        float x = ss + g_smax;
        float m = (x >= 0.f) ? x : ALPHA * x;
        c1_s[tid] = __expf(ss - m);
        c2_s[tid] = __expf(ALPHA * ss - m);
        thr_s[tid] = -ss;
    }

    // cp.async tile 0 of h
    {
        unsigned dst0 = (unsigned)__cvta_generic_to_shared(&h_s[0][0][0]);
        const float* src = g_h;  // j0 = 0
#pragma unroll
        for (int v = 0; v < 8; v++) {
            int e = v * 256 + tid;
            asm volatile("cp.async.cg.shared.global [%0], [%1], 16;"
                         :: "r"(dst0 + e * 16), "l"(src + e * 4));
        }
        asm volatile("cp.async.commit_group;");
    }

    // adj/sn prefetch for tile 0
    int av[8];
    float snv, e1v, e2v;
    {
        const int* ap = adj + (size_t)(r0 + w * 8) * Nn + lane;
#pragma unroll
        for (int ri = 0; ri < 8; ri++) av[ri] = ap[(size_t)ri * Nn];
        snv = g_sneigh[lane];
        e1v = g_e1[lane];
        e2v = g_e2[lane];
    }

    unsigned long long acc[8][4];
#pragma unroll
    for (int i = 0; i < 8; i++)
#pragma unroll
        for (int j = 0; j < 4; j++) acc[i][j] = 0ull;
    float zpart[8];
#pragma unroll
    for (int i = 0; i < 8; i++) zpart[i] = 0.f;

    __syncthreads();  // c1_s/c2_s/thr_s visible

    for (int t = 0; t < NT; t++) {
        int buf = t & 1;
        // ---- p fill for tile t (transposed, pre-duplicated) ----
#pragma unroll
        for (int ri = 0; ri < 8; ri++) {
            int r = w * 8 + ri;
            bool pos = snv >= thr_s[r];
            float c = pos ? c1_s[r] : c2_s[r];
            float e = pos ? e1v : e2v;
            float p = (av[ri] > 0) ? c * e : 0.f;
            zpart[ri] += p;
            p_s[lane][r] = packdup(p);
        }
        // ---- issue h cp.async + adj prefetch for tile t+1 ----
        if (t + 1 < NT) {
            int j0n = (t + 1) * KT;
            unsigned dst = (unsigned)__cvta_generic_to_shared(&h_s[buf ^ 1][0][0]);
            const float* src = g_h + (size_t)j0n * Ff;
#pragma unroll
            for (int v = 0; v < 8; v++) {
                int e = v * 256 + tid;
                asm volatile("cp.async.cg.shared.global [%0], [%1], 16;"
                             :: "r"(dst + e * 16), "l"(src + e * 4));
            }
            asm volatile("cp.async.commit_group;");
            const int* ap = adj + (size_t)(r0 + w * 8) * Nn + j0n + lane;
#pragma unroll
            for (int ri = 0; ri < 8; ri++) av[ri] = ap[(size_t)ri * Nn];
            snv = g_sneigh[j0n + lane];
            e1v = g_e1[j0n + lane];
            e2v = g_e2[j0n + lane];
            asm volatile("cp.async.wait_group 1;");
        } else {
            asm volatile("cp.async.wait_group 0;");
        }
        __syncthreads();
        // ---- FMA phase: 64x256x32 with packed f32x2 ----
#pragma unroll
        for (int k = 0; k < KT; k++) {
            ulonglong2 q0 = *(const ulonglong2*)&p_s[k][w * 8];
            ulonglong2 q1 = *(const ulonglong2*)&p_s[k][w * 8 + 2];
            ulonglong2 q2 = *(const ulonglong2*)&p_s[k][w * 8 + 4];
            ulonglong2 q3 = *(const ulonglong2*)&p_s[k][w * 8 + 6];
            unsigned long long pp[8] = {q0.x, q0.y, q1.x, q1.y,
                                        q2.x, q2.y, q3.x, q3.y};
            ulonglong2 h0 = *(const ulonglong2*)&h_s[buf][k][lane * 8];
            ulonglong2 h1 = *(const ulonglong2*)&h_s[buf][k][lane * 8 + 4];
            unsigned long long hh[4] = {h0.x, h0.y, h1.x, h1.y};
#pragma unroll
            for (int ri = 0; ri < 8; ri++)
#pragma unroll
                for (int c = 0; c < 4; c++)
                    acc[ri][c] = ffma2(pp[ri], hh[c], acc[ri][c]);
        }
        __syncthreads();
    }

    // ---- epilogue: Z reduce, divide, ELU, store ----
#pragma unroll
    for (int ri = 0; ri < 8; ri++) {
        float z = zpart[ri];
#pragma unroll
        for (int o = 16; o; o >>= 1) z += __shfl_xor_sync(0xffffffffu, z, o);
        float invz = 1.0f / z;
        int r = w * 8 + ri;
        float o0[8];
#pragma unroll
        for (int c = 0; c < 4; c++) {
            float2 f = unpack2(acc[ri][c]);
            float v0 = f.x * invz, v1 = f.y * invz;
            o0[2 * c] = (v0 > 0.f) ? v0 : expm1f(v0);
            o0[2 * c + 1] = (v1 > 0.f) ? v1 : expm1f(v1);
        }
        float* dst = out + (size_t)(r0 + r) * Ff + lane * 8;
        *(float4*)dst = make_float4(o0[0], o0[1], o0[2], o0[3]);
        *(float4*)(dst + 4) = make_float4(o0[4], o0[5], o0[6], o0[7]);
    }
}

// ================= launcher =================
extern "C" void kernel_launch(void* const* d_in, const int* in_sizes, int n_in,
                              void* d_out, int out_size) {
    const float* input = (const float*)d_in[0];
    const int*   adj   = (const int*)d_in[1];
    const float* W     = (const float*)d_in[2];
    const float* a     = (const float*)d_in[3];
    float* out = (float*)d_out;

    static int smem_set = 0;
    const int SMEM = 2 * KT * Ff * 4 + KT * PSTR * 8;  // 64KB + 17KB
    if (!smem_set) {
        cudaFuncSetAttribute(attn_main_kernel,
                             cudaFuncAttributeMaxDynamicSharedMemorySize, SMEM);
        smem_set = 1;
    }

    dim3 g1(Ff / 64, Nn / 64);
    gemm_h_kernel<<<g1, 256>>>(input, W);
    attn_vec_kernel<<<Nn, 256>>>(a);
    smax_kernel<<<1, 1024>>>();
    attn_main_kernel<<<Nn / BM, 256, SMEM>>>(adj, out);
}

// round 4
// speedup vs baseline: 2.2012x; 1.9553x over previous
#include <cuda_runtime.h>
#include <cstdint>

#define Nn 8192
#define KIN 512
#define Ff 256
#define ALPHA 0.2f

#define BM 64
#define KC 64
#define NT (Nn / KC)      // 128

// ---------------- scratch ----------------
__device__ float g_h[Nn * Ff];          // h = X@W (fp32)
__device__ uint32_t g_ht[Ff * Nn];      // h^T as tf32 bits, k-permuted within 8-groups
__device__ float g_sself[Nn];
__device__ float g_sneigh[Nn];
__device__ float g_e1[Nn];              // exp(s_neigh)
__device__ float g_e2[Nn];              // exp(ALPHA*s_neigh)
__device__ float g_smax;

// ---------------- helpers ----------------
__device__ __forceinline__ uint32_t f2tf32(float f) {
    uint32_t r;
    asm("cvt.rna.tf32.f32 %0, %1;" : "=r"(r) : "f"(f));
    return r;
}
// perm within an 8-k group so (k, k+4) are adjacent columns
__device__ __forceinline__ int kperm(int j) {
    return (j & ~7) + 2 * (j & 3) + ((j >> 2) & 1);
}
__device__ __forceinline__ void mma_tf32(float* d, uint32_t a0, uint32_t a1,
                                         uint32_t a2, uint32_t a3,
                                         uint32_t b0, uint32_t b1) {
    asm volatile(
        "mma.sync.aligned.m16n8k8.row.col.f32.tf32.tf32.f32 "
        "{%0,%1,%2,%3}, {%4,%5,%6,%7}, {%8,%9}, {%0,%1,%2,%3};"
        : "+f"(d[0]), "+f"(d[1]), "+f"(d[2]), "+f"(d[3])
        : "r"(a0), "r"(a1), "r"(a2), "r"(a3), "r"(b0), "r"(b1));
}

// ================= kernel 1: h = X @ W =================
__global__ __launch_bounds__(256, 1) void gemm_h_kernel(
    const float* __restrict__ A, const float* __restrict__ B) {
    __shared__ float As[32][65];
    __shared__ float Bs[32][64];
    int tid = threadIdx.x;
    int tx = tid & 15, ty = tid >> 4;
    int m0 = blockIdx.y * 64, n0 = blockIdx.x * 64;
    float acc[4][4];
#pragma unroll
    for (int i = 0; i < 4; i++)
#pragma unroll
        for (int j = 0; j < 4; j++) acc[i][j] = 0.f;
    for (int k0 = 0; k0 < KIN; k0 += 32) {
#pragma unroll
        for (int v = 0; v < 8; v++) {
            int idx = v * 256 + tid;
            int m = idx >> 5, k = idx & 31;
            As[k][m] = A[(size_t)(m0 + m) * KIN + k0 + k];
        }
#pragma unroll
        for (int v = 0; v < 8; v++) {
            int idx = v * 256 + tid;
            int k = idx >> 6, n = idx & 63;
            Bs[k][n] = B[(size_t)(k0 + k) * Ff + n0 + n];
        }
        __syncthreads();
#pragma unroll
        for (int k = 0; k < 32; k++) {
            float a0[4], b0[4];
#pragma unroll
            for (int i = 0; i < 4; i++) a0[i] = As[k][ty * 4 + i];
            float4 bv = *(const float4*)&Bs[k][tx * 4];
            b0[0] = bv.x; b0[1] = bv.y; b0[2] = bv.z; b0[3] = bv.w;
#pragma unroll
            for (int i = 0; i < 4; i++)
#pragma unroll
                for (int j = 0; j < 4; j++) acc[i][j] += a0[i] * b0[j];
        }
        __syncthreads();
    }
#pragma unroll
    for (int i = 0; i < 4; i++) {
        float4 o = make_float4(acc[i][0], acc[i][1], acc[i][2], acc[i][3]);
        *(float4*)&g_h[(size_t)(m0 + ty * 4 + i) * Ff + n0 + tx * 4] = o;
    }
}

// ================= kernel 1b: transpose + tf32 convert (k-permuted) =================
__global__ __launch_bounds__(256) void transpose_tf32_kernel() {
    __shared__ float ts[64][65];
    int m0 = blockIdx.x * 64;   // j
    int n0 = blockIdx.y * 64;   // f
    int tid = threadIdx.x;
    int c = tid & 63, r = tid >> 6;
#pragma unroll
    for (int rr = 0; rr < 16; rr++)
        ts[r + rr * 4][c] = g_h[(size_t)(m0 + r + rr * 4) * Ff + n0 + c];
    __syncthreads();
    int nl = tid >> 2;          // f local 0..63
    int mb = (tid & 3) * 16;    // j base
    uint32_t* dst = g_ht + (size_t)(n0 + nl) * Nn + m0;
#pragma unroll
    for (int q = 0; q < 16; q++) {
        int j = mb + q;
        dst[kperm(j)] = f2tf32(ts[j][nl]);
    }
}

// ================= kernel 2: s_self / s_neigh (+ e1,e2) =================
__global__ __launch_bounds__(256) void attn_vec_kernel(const float* __restrict__ a) {
    int i = blockIdx.x;
    int t = threadIdx.x;
    float v = g_h[(size_t)i * Ff + t];
    float p1 = v * a[t];
    float p2 = v * a[Ff + t];
#pragma unroll
    for (int o = 16; o; o >>= 1) {
        p1 += __shfl_down_sync(0xffffffffu, p1, o);
        p2 += __shfl_down_sync(0xffffffffu, p2, o);
    }
    __shared__ float s1[8], s2[8];
    if ((t & 31) == 0) { s1[t >> 5] = p1; s2[t >> 5] = p2; }
    __syncthreads();
    if (t == 0) {
        float a1 = 0.f, a2 = 0.f;
#pragma unroll
        for (int w = 0; w < 8; w++) { a1 += s1[w]; a2 += s2[w]; }
        g_sself[i] = a1;
        g_sneigh[i] = a2;
        g_e1[i] = __expf(a2);
        g_e2[i] = __expf(ALPHA * a2);
    }
}

// ================= kernel 3: global max of s_neigh =================
__global__ void smax_kernel() {
    int t = threadIdx.x;
    float m = -1e30f;
    for (int j = t; j < Nn; j += 1024) m = fmaxf(m, g_sneigh[j]);
#pragma unroll
    for (int o = 16; o; o >>= 1) m = fmaxf(m, __shfl_down_sync(0xffffffffu, m, o));
    __shared__ float sm[32];
    if ((t & 31) == 0) sm[t >> 5] = m;
    __syncthreads();
    if (t == 0) {
        float mm = sm[0];
#pragma unroll
        for (int w = 1; w < 32; w++) mm = fmaxf(mm, sm[w]);
        g_smax = mm;
    }
}

// ================= kernel 4: tf32 HMMA masked softmax-GEMM =================
// out[r] = elu( (sum_j p_rj h_j) / Z_r ),  p factorized: adj * c{1,2}[r] * e{1,2}[j]
#define PSTR 72   // ps row stride in u32
__global__ __launch_bounds__(256, 1) void attn_main_kernel(
    const int* __restrict__ adj, float* __restrict__ out) {
    __shared__ uint32_t ps[2][BM * PSTR];   // 36.9 KB, k-permuted P tiles (tf32 bits)
    __shared__ float zs[BM];

    int tid = threadIdx.x, w = tid >> 5, lane = tid & 31;
    int g = lane >> 2, t4 = lane & 3;
    int r0 = blockIdx.x * BM;

    // ---- per-thread row constants for P-gen (rows w*8 .. w*8+7) ----
    float c1r[8], c2r[8], thrr[8];
    float smax = g_smax;
#pragma unroll
    for (int ri = 0; ri < 8; ri++) {
        float ss = g_sself[r0 + w * 8 + ri];
        float x = ss + smax;
        float m = (x >= 0.f) ? x : ALPHA * x;
        c1r[ri] = __expf(ss - m);
        c2r[ri] = __expf(ALPHA * ss - m);
        thrr[ri] = -ss;
    }

    // gen-side column slots (fixed per thread)
    int j0 = 2 * lane;
    int c0 = kperm(j0), c1c = kperm(j0 + 1);

    // prefetch chunk 0
    const int* abase = adj + (size_t)(r0 + w * 8) * Nn;
    int2 av[8];
    float2 e1v, e2v, snv;
#pragma unroll
    for (int ri = 0; ri < 8; ri++) av[ri] = *(const int2*)(abase + (size_t)ri * Nn + j0);
    e1v = *(const float2*)&g_e1[j0];
    e2v = *(const float2*)&g_e2[j0];
    snv = *(const float2*)&g_sneigh[j0];

    // mma-side indexing: warp (wm, wn): rows wm*32.., cols wn*64..
    int wm = w & 1, wn = w >> 1;
    float acc[2][8][4];
#pragma unroll
    for (int mt = 0; mt < 2; mt++)
#pragma unroll
        for (int s = 0; s < 8; s++)
#pragma unroll
            for (int q = 0; q < 4; q++) acc[mt][s][q] = 0.f;
    float zpart[8];
#pragma unroll
    for (int ri = 0; ri < 8; ri++) zpart[ri] = 0.f;

    const uint32_t* btbase = g_ht + (size_t)(wn * 64 + g) * Nn + 2 * t4;

    for (int tch = 0; tch < NT; tch++) {
        int buf = tch & 1;
        // ---- P gen into ps[buf] ----
        uint32_t* pw = &ps[buf][(w * 8) * PSTR];
#pragma unroll
        for (int ri = 0; ri < 8; ri++) {
            int2 a = av[ri];
            bool pos0 = snv.x >= thrr[ri];
            float p0 = (pos0 ? c1r[ri] : c2r[ri]) * (pos0 ? e1v.x : e2v.x);
            p0 = (a.x > 0) ? p0 : 0.f;
            bool pos1 = snv.y >= thrr[ri];
            float p1 = (pos1 ? c1r[ri] : c2r[ri]) * (pos1 ? e1v.y : e2v.y);
            p1 = (a.y > 0) ? p1 : 0.f;
            zpart[ri] += p0 + p1;
            pw[ri * PSTR + c0] = f2tf32(p0);
            pw[ri * PSTR + c1c] = f2tf32(p1);
        }
        // ---- prefetch next chunk's adj / e / sn ----
        if (tch + 1 < NT) {
            int jn = (tch + 1) * KC + j0;
#pragma unroll
            for (int ri = 0; ri < 8; ri++)
                av[ri] = *(const int2*)(abase + (size_t)ri * Nn + jn);
            e1v = *(const float2*)&g_e1[jn];
            e2v = *(const float2*)&g_e2[jn];
            snv = *(const float2*)&g_sneigh[jn];
        }
        __syncthreads();

        // ---- MMA phase: warp tile 32x64, K=64 ----
        const uint32_t* bt = btbase + (size_t)tch * KC;   // [f][perm j] rows via +s*8*Nn
        const uint32_t* pa = &ps[buf][(wm * 32) * PSTR + 2 * t4];
#pragma unroll
        for (int k = 0; k < 8; k++) {
            // A frags for both m-tiles: LDS.64 pairs (k=t4, t4+4 adjacent after perm)
            uint2 a0 = *(const uint2*)(pa + (0 * 16 + g) * PSTR + k * 8);
            uint2 a1 = *(const uint2*)(pa + (0 * 16 + g + 8) * PSTR + k * 8);
            uint2 a2 = *(const uint2*)(pa + (1 * 16 + g) * PSTR + k * 8);
            uint2 a3 = *(const uint2*)(pa + (1 * 16 + g + 8) * PSTR + k * 8);
#pragma unroll
            for (int s = 0; s < 8; s++) {
                uint2 b = __ldg((const uint2*)(bt + (size_t)(s * 8) * Nn + k * 8));
                mma_tf32(acc[0][s], a0.x, a1.x, a0.y, a1.y, b.x, b.y);
                mma_tf32(acc[1][s], a2.x, a3.x, a2.y, a3.y, b.x, b.y);
            }
        }
        __syncthreads();
    }

    // ---- Z reduce to smem ----
#pragma unroll
    for (int ri = 0; ri < 8; ri++) {
        float z = zpart[ri];
#pragma unroll
        for (int o = 16; o; o >>= 1) z += __shfl_xor_sync(0xffffffffu, z, o);
        if (lane == 0) zs[w * 8 + ri] = z;
    }
    __syncthreads();

    // ---- epilogue: /Z, ELU, store ----
#pragma unroll
    for (int mt = 0; mt < 2; mt++) {
#pragma unroll
        for (int half = 0; half < 2; half++) {
            int rl = wm * 32 + mt * 16 + g + half * 8;
            float invz = 1.0f / zs[rl];
            float* orow = out + (size_t)(r0 + rl) * Ff + wn * 64 + 2 * t4;
#pragma unroll
            for (int s = 0; s < 8; s++) {
                float v0 = acc[mt][s][2 * half] * invz;
                float v1 = acc[mt][s][2 * half + 1] * invz;
                float2 o;
                o.x = (v0 > 0.f) ? v0 : expm1f(v0);
                o.y = (v1 > 0.f) ? v1 : expm1f(v1);
                *(float2*)(orow + s * 8) = o;
            }
        }
    }
}

// ================= launcher =================
extern "C" void kernel_launch(void* const* d_in, const int* in_sizes, int n_in,
                              void* d_out, int out_size) {
    const float* input = (const float*)d_in[0];
    const int*   adj   = (const int*)d_in[1];
    const float* W     = (const float*)d_in[2];
    const float* a     = (const float*)d_in[3];
    float* out = (float*)d_out;

    dim3 g1(Ff / 64, Nn / 64);
    gemm_h_kernel<<<g1, 256>>>(input, W);
    dim3 g2(Nn / 64, Ff / 64);
    transpose_tf32_kernel<<<g2, 256>>>();
    attn_vec_kernel<<<Nn, 256>>>(a);
    smax_kernel<<<1, 1024>>>();
    attn_main_kernel<<<Nn / BM, 256>>>(adj, out);
}